// round 15
// baseline (speedup 1.0000x reference)
#include <cuda_runtime.h>

#define Bx 2
#define Nx 32
#define Cx 128
#define Px 8192
#define NB 64
#define G3x 8
#define NEGV (-1e30f)

#define NTILES 2048                  // 32x32 transpose tiles
#define K1_GRID (NTILES + NB * 8)    // 2048 tile CTAs + 512 segment CTAs

// Scratch (static device globals — allowed)
__device__ float g_featT[(size_t)Bx * Px * Cx];  // transposed features [b][p][c]
__device__ int   g_idx[NB * Px];                 // per-box per-segment compacted lists
__device__ int   g_segcnt[NB * 8];               // per-box per-segment counts

// ---------------------------------------------------------------------------
// K1 (unchanged from R14): max-parallel prep.
//   CTA g < NTILES  : transpose ONE 32(C)x32(P) tile (skip if p0 >= offset[b]).
//   CTA g >= NTILES : ordered compaction of segment k of box bn.
// ---------------------------------------------------------------------------
__global__ void __launch_bounds__(256) roipool_prep_kernel(
    const float* __restrict__ feat,    // [B][C][P]
    const float* __restrict__ boxes,   // [B][N][6]
    const int*   __restrict__ offset,  // [B]
    const float* __restrict__ pc)      // [B][P][3]
{
    const int g = blockIdx.x;
    const int t = threadIdx.x;

    if (g < NTILES) {
        __shared__ __align__(16) float s_tile[32][33];
        const int p0 = (g & 255) * 32;
        const int c0 = ((g >> 8) & 3) * 32;
        const int b  = g >> 10;
        if (p0 >= __ldg(offset + b)) return;         // rows never referenced

        const int tx = t & 7, ty = t >> 3;
        const float4 v = *(const float4*)(feat + (size_t)b * Cx * Px
                                          + (size_t)(c0 + ty) * Px + p0 + tx * 4);
        s_tile[ty][tx * 4 + 0] = v.x;
        s_tile[ty][tx * 4 + 1] = v.y;
        s_tile[ty][tx * 4 + 2] = v.z;
        s_tile[ty][tx * 4 + 3] = v.w;
        __syncthreads();

        const int cx = t & 7, py = t >> 3;
        float4 o;
        o.x = s_tile[cx * 4 + 0][py];
        o.y = s_tile[cx * 4 + 1][py];
        o.z = s_tile[cx * 4 + 2][py];
        o.w = s_tile[cx * 4 + 3][py];
        *(float4*)(g_featT + (size_t)b * Px * Cx
                   + (size_t)(p0 + py) * Cx + c0 + cx * 4) = o;
        return;
    }

    // ---- compaction: segment k of box bn, ordered, flags in registers ----
    __shared__ int s_wcnt[8];
    const int seg  = g - NTILES;
    const int bn   = seg >> 3;
    const int k    = seg & 7;
    const int bb   = bn >> 5;
    const int lane = t & 31;
    const int w    = t >> 5;

    const float bx0 = __ldg(boxes + bn * 6 + 0);
    const float by0 = __ldg(boxes + bn * 6 + 1);
    const float bz0 = __ldg(boxes + bn * 6 + 2);
    const float hx  = __ldg(boxes + bn * 6 + 3) * 0.5f;
    const float hy  = __ldg(boxes + bn * 6 + 4) * 0.5f;
    const float hz  = __ldg(boxes + bn * 6 + 5) * 0.5f;
    const float lox = bx0 - hx, hix = bx0 + hx;
    const float loy = by0 - hy, hiy = by0 + hy;
    const float loz = bz0 - hz, hiz = bz0 + hz;

    const int offb = __ldg(offset + bb);
    const float* pcb = pc + (size_t)bb * Px * 3;
    const int wseg = k * 1024 + w * 128;             // this warp's 128 points

    float qx[4], qy[4], qz[4];
#pragma unroll
    for (int i = 0; i < 4; i++) {
        const int p = wseg + i * 32 + lane;
        if (p < offb) {
            qx[i] = __ldg(pcb + p * 3 + 0);
            qy[i] = __ldg(pcb + p * 3 + 1);
            qz[i] = __ldg(pcb + p * 3 + 2);
        }
    }

    unsigned bal[4];
    unsigned fl = 0;
    int cntw = 0;
#pragma unroll
    for (int i = 0; i < 4; i++) {
        const int p = wseg + i * 32 + lane;
        bool flag = false;
        if (p < offb)
            flag = (qx[i] >= lox) & (qx[i] <= hix) &
                   (qy[i] >= loy) & (qy[i] <= hiy) &
                   (qz[i] >= loz) & (qz[i] <= hiz);
        bal[i] = __ballot_sync(0xffffffffu, flag);
        fl |= ((unsigned)flag) << i;
        cntw += __popc(bal[i]);
    }
    if (lane == 0) s_wcnt[w] = cntw;
    __syncthreads();

    int base = 0, tot = 0;
#pragma unroll
    for (int ww = 0; ww < 8; ww++) {
        if (ww < w) base += s_wcnt[ww];
        tot += s_wcnt[ww];
    }
    int* gi = g_idx + bn * Px + k * 1024;
#pragma unroll
    for (int i = 0; i < 4; i++) {
        if ((fl >> i) & 1u)
            gi[base + __popc(bal[i] & ((1u << lane) - 1u))] = wseg + i * 32 + lane;
        base += __popc(bal[i]);
    }
    if (t == 0) g_segcnt[bn * 8 + k] = tot;
}

// ---------------------------------------------------------------------------
// K2: ONE FAT CTA PER BOX. 64 CTAs x 1024 threads.
//  - load the 8-count line once, stage the whole ordered list once (smem),
//  - thread t = (bin k = t>>7, channel c = t&127): bin-range max with
//    batch-8 independent coalesced loads (lanes = consecutive channels).
// Kills the 512x replicated serial chain of previous K2 designs.
// ---------------------------------------------------------------------------
__global__ void __launch_bounds__(1024, 1) roipool_max_kernel(
    float* __restrict__ out)               // [B][N][C][8]
{
    __shared__ int s_list[Px];              // full ordered index list (<=32KB)

    const int bn = blockIdx.x;
    const int bb = bn >> 5;
    const int t  = threadIdx.x;

    // segment counts (one 32B line, broadcast)
    int c[8];
#pragma unroll
    for (int s = 0; s < 8; s++) c[s] = g_segcnt[bn * 8 + s];
    int cnt = 0;
#pragma unroll
    for (int s = 0; s < 8; s++) cnt += c[s];

    // stage the whole box's ordered list: rank r -> (seg, loc) -> index
    for (int r = t; r < cnt; r += 1024) {
        int acc = 0, seg = 0, loc = 0;
#pragma unroll
        for (int s = 0; s < 8; s++) {
            const int nxt = acc + c[s];
            if (r >= acc && r < nxt) { seg = s; loc = r - acc; }
            acc = nxt;
        }
        s_list[r] = g_idx[bn * Px + seg * 1024 + loc];
    }
    __syncthreads();

    // thread t: bin k, channel ch
    const int k  = t >> 7;
    const int ch = t & 127;
    const int st = (k * cnt) >> 3;                   // floor(k*cnt/8)
    const int en = ((k + 1) * cnt + 7) >> 3;         // ceil((k+1)*cnt/8)

    const float* fb = g_featT + (size_t)bb * Px * Cx + ch;
    float m0 = NEGV, m1 = NEGV, m2 = NEGV, m3 = NEGV;
    int r = st;
    for (; r + 7 < en; r += 8) {                     // batch-8 for MLP
        const float v0 = fb[(size_t)s_list[r + 0] * Cx];
        const float v1 = fb[(size_t)s_list[r + 1] * Cx];
        const float v2 = fb[(size_t)s_list[r + 2] * Cx];
        const float v3 = fb[(size_t)s_list[r + 3] * Cx];
        const float v4 = fb[(size_t)s_list[r + 4] * Cx];
        const float v5 = fb[(size_t)s_list[r + 5] * Cx];
        const float v6 = fb[(size_t)s_list[r + 6] * Cx];
        const float v7 = fb[(size_t)s_list[r + 7] * Cx];
        m0 = fmaxf(m0, fmaxf(v0, v4));
        m1 = fmaxf(m1, fmaxf(v1, v5));
        m2 = fmaxf(m2, fmaxf(v2, v6));
        m3 = fmaxf(m3, fmaxf(v3, v7));
    }
    for (; r < en; r++)
        m0 = fmaxf(m0, fb[(size_t)s_list[r] * Cx]);

    const float m = fmaxf(fmaxf(m0, m1), fmaxf(m2, m3));
    out[((size_t)bn * Cx + ch) * G3x + k] = (cnt > 0) ? m : 0.0f;
}

// ---------------------------------------------------------------------------
// Harness entry — two launches, kernel boundary = global sync
// ---------------------------------------------------------------------------
extern "C" void kernel_launch(void* const* d_in, const int* in_sizes, int n_in,
                              void* d_out, int out_size)
{
    const float* boxes  = (const float*)d_in[0];   // (B, N, 6)
    const float* feat   = (const float*)d_in[1];   // (B, C, P)
    const int*   offset = (const int*)  d_in[2];   // (B,)
    const float* pc     = (const float*)d_in[3];   // (B, P, 3)
    float*       out    = (float*)d_out;           // (B, N, C, 2, 2, 2)

    roipool_prep_kernel<<<K1_GRID, 256>>>(feat, boxes, offset, pc);
    roipool_max_kernel<<<NB, 1024>>>(out);
}

// round 16
// speedup vs baseline: 1.2393x; 1.2393x over previous
#include <cuda_runtime.h>

#define Bx 2
#define Nx 32
#define Cx 128
#define Px 8192
#define NB 64
#define G3x 8
#define NEGV (-1e30f)
#define GRIDX 512

// Scratch (static device globals — allowed)
__device__ float    g_featT[(size_t)Bx * Px * Cx];  // transposed features [b][p][c]
__device__ int      g_idx[NB * Px];                 // per-box per-segment compacted lists
__device__ int      g_segcnt[NB * 8];               // per-box per-segment counts
__device__ unsigned g_bar = 0;                      // barrier arrival counter
__device__ unsigned g_rel = 0;                      // barrier release epoch (sense flag)

// ---------------------------------------------------------------------------
// One kernel, 512 CTAs, uniform work per CTA = (box bn, bin k)  [R10 shape].
//  Pre-barrier: 4 transpose float4 LDGs (p-blocks strided over the 4 quarters
//    of [0,Px) -> balanced offset-skip), 12 pc LDGs for segment-k compaction,
//    all issued before the single work sync; then featT STG + ordered g_idx.
//  Grid barrier: release fence (all threads) -> sync -> arrivals via
//    atomicAdd; LAST arriver writes the epoch flag g_rel once; others poll
//    the read-only flag (no RMW interference) -> acquire fence -> sync.
//  Post-barrier: prefix of 8 segment counts -> bin [st,en), assemble indices
//    into smem (proven staging), coalesced float4 gather-max.
// ---------------------------------------------------------------------------
__global__ void __launch_bounds__(256, 4) roipool_fused_kernel(
    const float* __restrict__ feat,    // [B][C][P]
    const float* __restrict__ boxes,   // [B][N][6]
    const int*   __restrict__ offset,  // [B]
    const float* __restrict__ pc,      // [B][P][3]
    float*       __restrict__ out)     // [B][N][C][8]
{
    __shared__ __align__(16) float s_tile[4][32][33];
    __shared__ int   s_wcnt[8];
    __shared__ int   s_bin[1032];
    __shared__ __align__(16) float s_red[8][128];

    const int g    = blockIdx.x;
    const int t    = threadIdx.x;
    const int lane = t & 31;
    const int w    = t >> 5;
    const int bn   = g >> 3;        // box
    const int k    = g & 7;         // bin == segment
    const int bb   = bn >> 5;       // batch of this box

    const int off0 = __ldg(offset + 0);
    const int off1 = __ldg(offset + 1);

    // ---- transpose: CTA g owns (b = g>>8, cblock = (g>>6)&3,
    //      p-blocks {(g&63) + 64*i}) -> strided over all 4 quarters ----
    const int bt   = g >> 8;
    const int c0   = ((g >> 6) & 3) * 32;
    const int pidx = g & 63;
    const int offt = bt ? off1 : off0;
    const int tx = t & 7, ty = t >> 3;

    int    pb[4];
    bool   keep[4];
    float4 v[4];
#pragma unroll
    for (int i = 0; i < 4; i++) {
        pb[i]   = (pidx + 64 * i) * 32;
        keep[i] = pb[i] < offt;                      // rows never referenced -> skip
        if (keep[i])
            v[i] = *(const float4*)(feat + (size_t)bt * Cx * Px
                                    + (size_t)(c0 + ty) * Px + pb[i] + tx * 4);
    }

    // ---- box params (uniform __ldg broadcast; RO inputs) ----
    const float bx0 = __ldg(boxes + bn * 6 + 0);
    const float by0 = __ldg(boxes + bn * 6 + 1);
    const float bz0 = __ldg(boxes + bn * 6 + 2);
    const float hx  = __ldg(boxes + bn * 6 + 3) * 0.5f;
    const float hy  = __ldg(boxes + bn * 6 + 4) * 0.5f;
    const float hz  = __ldg(boxes + bn * 6 + 5) * 0.5f;
    const float lox = bx0 - hx, hix = bx0 + hx;
    const float loy = by0 - hy, hiy = by0 + hy;
    const float loz = bz0 - hz, hiz = bz0 + hz;

    // ---- pc loads for segment k (overlap transpose latency) ----
    const int offb = bb ? off1 : off0;
    const float* pcb = pc + (size_t)bb * Px * 3;
    const int wseg = k * 1024 + w * 128;             // this warp's 128 points

    float qx[4], qy[4], qz[4];
#pragma unroll
    for (int i = 0; i < 4; i++) {
        const int p = wseg + i * 32 + lane;
        if (p < offb) {
            qx[i] = __ldg(pcb + p * 3 + 0);
            qy[i] = __ldg(pcb + p * 3 + 1);
            qz[i] = __ldg(pcb + p * 3 + 2);
        }
    }

    // ---- STS tiles ----
#pragma unroll
    for (int i = 0; i < 4; i++) {
        if (keep[i]) {
            s_tile[i][ty][tx * 4 + 0] = v[i].x;
            s_tile[i][ty][tx * 4 + 1] = v[i].y;
            s_tile[i][ty][tx * 4 + 2] = v[i].z;
            s_tile[i][ty][tx * 4 + 3] = v[i].w;
        }
    }

    // ---- flags + ballots ----
    unsigned bal[4];
    unsigned fl = 0;
    int cntw = 0;
#pragma unroll
    for (int i = 0; i < 4; i++) {
        const int p = wseg + i * 32 + lane;
        bool flag = false;
        if (p < offb)
            flag = (qx[i] >= lox) & (qx[i] <= hix) &
                   (qy[i] >= loy) & (qy[i] <= hiy) &
                   (qz[i] >= loz) & (qz[i] <= hiz);
        bal[i] = __ballot_sync(0xffffffffu, flag);
        fl |= ((unsigned)flag) << i;
        cntw += __popc(bal[i]);
    }
    if (lane == 0) s_wcnt[w] = cntw;

    __syncthreads();                                 // single work-section sync

    // ---- featT stores ----
    {
        const int cx = t & 7, py = t >> 3;
        float* dst = g_featT + (size_t)bt * Px * Cx + (size_t)py * Cx + c0 + cx * 4;
#pragma unroll
        for (int i = 0; i < 4; i++) {
            if (keep[i]) {
                float4 o;
                o.x = s_tile[i][cx * 4 + 0][py];
                o.y = s_tile[i][cx * 4 + 1][py];
                o.z = s_tile[i][cx * 4 + 2][py];
                o.w = s_tile[i][cx * 4 + 3][py];
                *(float4*)(dst + (size_t)pb[i] * Cx) = o;
            }
        }
    }

    // ---- ordered segment-local compaction writes ----
    int base = 0, tot = 0;
#pragma unroll
    for (int ww = 0; ww < 8; ww++) {
        if (ww < w) base += s_wcnt[ww];
        tot += s_wcnt[ww];
    }
    int* gi = g_idx + bn * Px + k * 1024;
#pragma unroll
    for (int i = 0; i < 4; i++) {
        if ((fl >> i) & 1u)
            gi[base + __popc(bal[i] & ((1u << lane) - 1u))] = wseg + i * 32 + lane;
        base += __popc(bal[i]);
    }
    if (t == 0) g_segcnt[bn * 8 + k] = tot;

    // ---- grid barrier: arrivals on counter, release via epoch flag ----
    __threadfence();           // RELEASE: each thread publishes its own stores
    __syncthreads();           // all fences done before arrival
    if (t == 0) {
        const unsigned a = atomicAdd(&g_bar, 1u);
        const unsigned epoch = a / GRIDX + 1u;       // this launch's epoch
        if ((a + 1u) % GRIDX == 0u) {
            // last arriver: single release store (pollers read-only -> no
            // RMW/poll interference on the hot line)
            *(volatile unsigned*)&g_rel = epoch;
        } else {
            while (*(volatile unsigned*)&g_rel < epoch) __nanosleep(32);
        }
        __threadfence();       // ACQUIRE
    }
    __syncthreads();

    // ---- assemble bin k's index list (proven smem staging) ----
    int c[8];
#pragma unroll
    for (int s = 0; s < 8; s++) c[s] = g_segcnt[bn * 8 + s];
    int cnt = 0;
#pragma unroll
    for (int s = 0; s < 8; s++) cnt += c[s];

    const int st = (k * cnt) >> 3;                   // floor(k*cnt/8)
    const int en = ((k + 1) * cnt + 7) >> 3;         // ceil((k+1)*cnt/8)
    const int nb = en - st;                          // == 0 iff cnt == 0

    for (int j = t; j < nb; j += 256) {
        const int r = st + j;                        // global rank in this box
        int acc = 0, seg = 0, loc = 0;
#pragma unroll
        for (int s = 0; s < 8; s++) {
            const int nxt = acc + c[s];
            if (r >= acc && r < nxt) { seg = s; loc = r - acc; }
            acc = nxt;
        }
        s_bin[j] = g_idx[bn * Px + seg * 1024 + loc];
    }
    __syncthreads();

    // ---- gather max: 8 warps over points, lane = float4 channel group ----
    const float4* ftb = (const float4*)(g_featT + (size_t)bb * Px * Cx);
    float4 m = make_float4(NEGV, NEGV, NEGV, NEGV);
    for (int j = w; j < nb; j += 32) {               // batch-4 for MLP
        const int q0 = s_bin[j];
        const int q1 = (j + 8  < nb) ? s_bin[j + 8]  : q0;
        const int q2 = (j + 16 < nb) ? s_bin[j + 16] : q0;
        const int q3 = (j + 24 < nb) ? s_bin[j + 24] : q0;
        const float4 v0 = ftb[(size_t)q0 * 32 + lane];
        const float4 v1 = ftb[(size_t)q1 * 32 + lane];
        const float4 v2 = ftb[(size_t)q2 * 32 + lane];
        const float4 v3 = ftb[(size_t)q3 * 32 + lane];
        m.x = fmaxf(fmaxf(m.x, v0.x), fmaxf(fmaxf(v1.x, v2.x), v3.x));
        m.y = fmaxf(fmaxf(m.y, v0.y), fmaxf(fmaxf(v1.y, v2.y), v3.y));
        m.z = fmaxf(fmaxf(m.z, v0.z), fmaxf(fmaxf(v1.z, v2.z), v3.z));
        m.w = fmaxf(fmaxf(m.w, v0.w), fmaxf(fmaxf(v1.w, v2.w), v3.w));
    }
    *(float4*)&s_red[w][lane * 4] = m;
    __syncthreads();

    if (t < 128) {
        float r = s_red[0][t];
#pragma unroll
        for (int ww = 1; ww < 8; ww++) r = fmaxf(r, s_red[ww][t]);
        out[((size_t)bn * Cx + t) * G3x + k] = (cnt > 0) ? r : 0.0f;
    }
}

// ---------------------------------------------------------------------------
// Harness entry — single launch
// ---------------------------------------------------------------------------
extern "C" void kernel_launch(void* const* d_in, const int* in_sizes, int n_in,
                              void* d_out, int out_size)
{
    const float* boxes  = (const float*)d_in[0];   // (B, N, 6)
    const float* feat   = (const float*)d_in[1];   // (B, C, P)
    const int*   offset = (const int*)  d_in[2];   // (B,)
    const float* pc     = (const float*)d_in[3];   // (B, P, 3)
    float*       out    = (float*)d_out;           // (B, N, C, 2, 2, 2)

    roipool_fused_kernel<<<GRIDX, 256>>>(feat, boxes, offset, pc, out);
}